// round 1
// baseline (speedup 1.0000x reference)
#include <cuda_runtime.h>
#include <math.h>

#define SEQ 4096
#define HID 1024
#define NH  16
#define HD  64

// Scratch (allocation-free rule: __device__ globals)
__device__ float g_Q[SEQ * HID];
__device__ float g_K[SEQ * HID];
__device__ float g_V[SEQ * HID];
__device__ float g_C[SEQ * HID];

// ---------------------------------------------------------------------------
// GEMM: C[M,N] = A[M,K] @ B[N,K]^T (+ optional bias[N])
// BM=BN=128, BK=32, 256 threads, 8x8 micro-tile per thread.
// Row-major smem with +1 pad: conflict-free STS and LDS.
// ---------------------------------------------------------------------------
template <bool BIAS>
__global__ __launch_bounds__(256, 2)
void gemm_bt(const float* __restrict__ A, const float* __restrict__ B,
             const float* __restrict__ bias, float* __restrict__ C,
             int M, int N, int K) {
    __shared__ float As[128][33];
    __shared__ float Bs[128][33];

    const int tid = threadIdx.x;
    const int tx = tid & 15;   // col group 0..15
    const int ty = tid >> 4;   // row group 0..15
    const int rowBase = blockIdx.y * 128;
    const int colBase = blockIdx.x * 128;

    float acc[8][8];
#pragma unroll
    for (int i = 0; i < 8; i++)
#pragma unroll
        for (int j = 0; j < 8; j++) acc[i][j] = 0.f;

    for (int k0 = 0; k0 < K; k0 += 32) {
#pragma unroll
        for (int t = 0; t < 16; t++) {
            int i = tid + t * 256;
            int r = i >> 5, c = i & 31;
            As[r][c] = A[(rowBase + r) * K + k0 + c];
            Bs[r][c] = B[(colBase + r) * K + k0 + c];
        }
        __syncthreads();
#pragma unroll 4
        for (int k = 0; k < 32; k++) {
            float a[8], b[8];
#pragma unroll
            for (int i = 0; i < 8; i++) a[i] = As[ty * 8 + i][k];
#pragma unroll
            for (int j = 0; j < 8; j++) b[j] = Bs[tx * 8 + j][k];
#pragma unroll
            for (int i = 0; i < 8; i++)
#pragma unroll
                for (int j = 0; j < 8; j++)
                    acc[i][j] += a[i] * b[j];
        }
        __syncthreads();
    }

#pragma unroll
    for (int i = 0; i < 8; i++) {
        int r = rowBase + ty * 8 + i;
#pragma unroll
        for (int j = 0; j < 8; j++) {
            int c = colBase + tx * 8 + j;
            float v = acc[i][j];
            if (BIAS) v += bias[c];
            C[r * N + c] = v;
        }
    }
}

// ---------------------------------------------------------------------------
// RoPE, in place on Q and K. One thread per (seq, head, pair j<32).
// ---------------------------------------------------------------------------
__global__ void rope_kernel(float* __restrict__ Q, float* __restrict__ K,
                            const int* __restrict__ pos_ids) {
    int idx = blockIdx.x * blockDim.x + threadIdx.x;
    const int total = SEQ * NH * (HD / 2);
    if (idx >= total) return;
    int j = idx & 31;
    int h = (idx >> 5) & (NH - 1);
    int s = idx >> 9;  // /(32*16)

    float pos = (float)pos_ids[s];
    // theta = 10000^(-2j/64) = exp(-(j/32)*ln(10000))
    float theta = expf(-(float)j * (9.210340371976184f / 32.0f));
    float ang = pos * theta;
    float sn, cs;
    sincosf(ang, &sn, &cs);

    int base = s * HID + h * HD + j;
    float q1 = Q[base], q2 = Q[base + 32];
    Q[base]      = q1 * cs - q2 * sn;
    Q[base + 32] = q1 * sn + q2 * cs;
    float k1 = K[base], k2 = K[base + 32];
    K[base]      = k1 * cs - k2 * sn;
    K[base + 32] = k1 * sn + k2 * cs;
}

// ---------------------------------------------------------------------------
// Causal flash attention, fp32. BR=128 query rows, BC=64 key cols per tile.
// 256 threads, 8x4 micro-tile. Online softmax (m, l) per row in smem.
// grid = (SEQ/128, NH); heavy (late-diagonal) blocks scheduled first.
// ---------------------------------------------------------------------------
__global__ __launch_bounds__(256, 2)
void flash_attn(const float* __restrict__ Q, const float* __restrict__ K,
                const float* __restrict__ V, float* __restrict__ O) {
    extern __shared__ float sm[];
    float* Qs = sm;                 // 128 x 65
    float* Ks = Qs + 128 * 65;      // 64 x 65
    float* Vs = Ks + 64 * 65;       // 64 x 65
    float* Ps = Vs + 64 * 65;       // 128 x 65
    float* mrow = Ps + 128 * 65;    // 128
    float* lrow = mrow + 128;       // 128
    float* arow = lrow + 128;       // 128

    const int tid = threadIdx.x;
    const int tx = tid & 15;   // 0..15 -> 4 cols each
    const int ty = tid >> 4;   // 0..15 -> 8 rows each
    const int qb = gridDim.x - 1 - blockIdx.x;   // heavy blocks first
    const int h = blockIdx.y;
    const int qBase = qb * 128;
    const float scale = 0.125f;  // 1/sqrt(64)

    for (int i = tid; i < 128 * HD; i += 256) {
        int r = i >> 6, c = i & 63;
        Qs[r * 65 + c] = Q[(qBase + r) * HID + h * HD + c];
    }
    if (tid < 128) { mrow[tid] = -1e30f; lrow[tid] = 0.f; }

    float o[8][4];
#pragma unroll
    for (int i = 0; i < 8; i++)
#pragma unroll
        for (int j = 0; j < 4; j++) o[i][j] = 0.f;
    __syncthreads();

    const int nkb = 2 * qb + 2;
    for (int kb = 0; kb < nkb; kb++) {
        const int kBase = kb * 64;
        for (int i = tid; i < 64 * HD; i += 256) {
            int r = i >> 6, c = i & 63;
            Ks[r * 65 + c] = K[(kBase + r) * HID + h * HD + c];
            Vs[r * 65 + c] = V[(kBase + r) * HID + h * HD + c];
        }
        __syncthreads();

        // S = Q K^T (8x4 per thread)
        float s[8][4];
#pragma unroll
        for (int i = 0; i < 8; i++)
#pragma unroll
            for (int j = 0; j < 4; j++) s[i][j] = 0.f;
#pragma unroll 4
        for (int k = 0; k < HD; k++) {
            float a[8], b[4];
#pragma unroll
            for (int i = 0; i < 8; i++) a[i] = Qs[(ty * 8 + i) * 65 + k];
#pragma unroll
            for (int j = 0; j < 4; j++) b[j] = Ks[(tx * 4 + j) * 65 + k];
#pragma unroll
            for (int i = 0; i < 8; i++)
#pragma unroll
                for (int j = 0; j < 4; j++)
                    s[i][j] += a[i] * b[j];
        }

        const bool edge = (kBase + 63 > qBase);
#pragma unroll
        for (int i = 0; i < 8; i++) {
            int qg = qBase + ty * 8 + i;
#pragma unroll
            for (int j = 0; j < 4; j++) {
                int kg = kBase + tx * 4 + j;
                float v = s[i][j] * scale;
                if (edge && kg > qg) v = -1e30f;
                Ps[(ty * 8 + i) * 65 + tx * 4 + j] = v;
            }
        }
        __syncthreads();

        // Online softmax row update (one thread per row)
        if (tid < 128) {
            const int r = tid;
            float m_old = mrow[r];
            float mx = m_old;
#pragma unroll 8
            for (int c = 0; c < 64; c++) mx = fmaxf(mx, Ps[r * 65 + c]);
            float sum = 0.f;
#pragma unroll 8
            for (int c = 0; c < 64; c++) {
                float p = __expf(Ps[r * 65 + c] - mx);
                Ps[r * 65 + c] = p;
                sum += p;
            }
            float alpha = __expf(m_old - mx);
            arow[r] = alpha;
            mrow[r] = mx;
            lrow[r] = lrow[r] * alpha + sum;
        }
        __syncthreads();

        // O = alpha*O + P V
        float al[8];
#pragma unroll
        for (int i = 0; i < 8; i++) al[i] = arow[ty * 8 + i];
#pragma unroll
        for (int i = 0; i < 8; i++)
#pragma unroll
            for (int j = 0; j < 4; j++) o[i][j] *= al[i];
#pragma unroll 4
        for (int k = 0; k < 64; k++) {
            float p[8], v[4];
#pragma unroll
            for (int i = 0; i < 8; i++) p[i] = Ps[(ty * 8 + i) * 65 + k];
#pragma unroll
            for (int j = 0; j < 4; j++) v[j] = Vs[k * 65 + tx * 4 + j];
#pragma unroll
            for (int i = 0; i < 8; i++)
#pragma unroll
                for (int j = 0; j < 4; j++)
                    o[i][j] += p[i] * v[j];
        }
        __syncthreads();
    }

#pragma unroll
    for (int i = 0; i < 8; i++) {
        int r = qBase + ty * 8 + i;
        float inv = 1.f / lrow[ty * 8 + i];
#pragma unroll
        for (int j = 0; j < 4; j++)
            O[r * HID + h * HD + tx * 4 + j] = o[i][j] * inv;
    }
}

// ---------------------------------------------------------------------------
// Host launcher. Inputs (metadata order):
//   0:X f32[1,4096,1024]  1:position_ids i32[4096]  2:mask (unused)
//   3:Wq 4:Wk 5:Wv 6:Wo f32[1024,1024]  7:bo f32[1024]
// Output: f32[1,4096,1024]
// ---------------------------------------------------------------------------
extern "C" void kernel_launch(void* const* d_in, const int* in_sizes, int n_in,
                              void* d_out, int out_size) {
    const float* X  = (const float*)d_in[0];
    const int* pos  = (const int*)d_in[1];
    const float* Wq = (const float*)d_in[3];
    const float* Wk = (const float*)d_in[4];
    const float* Wv = (const float*)d_in[5];
    const float* Wo = (const float*)d_in[6];
    const float* bo = (const float*)d_in[7];
    float* out = (float*)d_out;

    float *Qd, *Kd, *Vd, *Cd;
    cudaGetSymbolAddress((void**)&Qd, g_Q);
    cudaGetSymbolAddress((void**)&Kd, g_K);
    cudaGetSymbolAddress((void**)&Vd, g_V);
    cudaGetSymbolAddress((void**)&Cd, g_C);

    dim3 ggrid(HID / 128, SEQ / 128);  // (8, 32)

    gemm_bt<false><<<ggrid, 256>>>(X, Wq, nullptr, Qd, SEQ, HID, HID);
    gemm_bt<false><<<ggrid, 256>>>(X, Wk, nullptr, Kd, SEQ, HID, HID);
    gemm_bt<false><<<ggrid, 256>>>(X, Wv, nullptr, Vd, SEQ, HID, HID);

    rope_kernel<<<(SEQ * NH * (HD / 2) + 255) / 256, 256>>>(Qd, Kd, pos);

    const int flash_smem = (128 * 65 + 64 * 65 + 64 * 65 + 128 * 65 + 3 * 128) * (int)sizeof(float);
    cudaFuncSetAttribute(flash_attn, cudaFuncAttributeMaxDynamicSharedMemorySize, flash_smem);
    flash_attn<<<dim3(SEQ / 128, NH), 256, flash_smem>>>(Qd, Kd, Vd, Cd);

    gemm_bt<true><<<ggrid, 256>>>(Cd, Wo, bo, out, SEQ, HID, HID);
}

// round 4
// speedup vs baseline: 2.9275x; 2.9275x over previous
#include <cuda_runtime.h>
#include <math.h>
#include <stdint.h>

#define SEQ 4096
#define HID 1024
#define NH  16
#define HD  64

// Scratch (allocation-free rule: __device__ globals)
__device__ float g_Q[SEQ * HID];
__device__ float g_K[SEQ * HID];
__device__ float g_V[SEQ * HID];
__device__ float g_C[SEQ * HID];

// ---------------------------------------------------------------------------
// helpers
// ---------------------------------------------------------------------------
__device__ __forceinline__ float tf32r(float x) {
    uint32_t u;
    asm("cvt.rna.tf32.f32 %0, %1;" : "=r"(u) : "f"(x));
    return __uint_as_float(u);
}

__device__ __forceinline__ void mma_tf32(float (&d)[4], const uint32_t (&a)[4],
                                         uint32_t b0, uint32_t b1) {
    asm volatile(
        "mma.sync.aligned.m16n8k8.row.col.f32.tf32.tf32.f32 "
        "{%0,%1,%2,%3}, {%4,%5,%6,%7}, {%8,%9}, {%0,%1,%2,%3};\n"
        : "+f"(d[0]), "+f"(d[1]), "+f"(d[2]), "+f"(d[3])
        : "r"(a[0]), "r"(a[1]), "r"(a[2]), "r"(a[3]), "r"(b0), "r"(b1));
}

// ---------------------------------------------------------------------------
// tf32 GEMM: C[M,N] = A[M,K] @ B[N,K]^T (+ optional bias[N])
// BM=BN=128, BK=32, 256 threads = 8 warps in 4(m) x 2(n); warp tile 32x64.
// Smem pitch 36 floats -> conflict-free fragment LDS.
// ---------------------------------------------------------------------------
template <bool BIAS>
__global__ __launch_bounds__(256)
void gemm_tf32(const float* __restrict__ A, const float* __restrict__ B,
               const float* __restrict__ bias, float* __restrict__ C,
               int M, int N, int K) {
    __shared__ float As[128 * 36];
    __shared__ float Bs[128 * 36];

    const int tid = threadIdx.x;
    const int lane = tid & 31;
    const int w = tid >> 5;
    const int wm = w & 3;       // 0..3 -> 32-row slab
    const int wn = w >> 2;      // 0..1 -> 64-col slab
    const int rowBase = blockIdx.y * 128;
    const int colBase = blockIdx.x * 128;

    float acc[16][4];  // [mt*8 + nt][4]
#pragma unroll
    for (int i = 0; i < 16; i++)
#pragma unroll
        for (int j = 0; j < 4; j++) acc[i][j] = 0.f;

    const int sr = tid >> 3;          // 0..31
    const int sc = (tid & 7) * 4;     // 0,4,...,28

    for (int k0 = 0; k0 < K; k0 += 32) {
#pragma unroll
        for (int t = 0; t < 4; t++) {
            int rr = sr + t * 32;
            float4 va = *(const float4*)&A[(rowBase + rr) * K + k0 + sc];
            float4 vb = *(const float4*)&B[(colBase + rr) * K + k0 + sc];
            As[rr * 36 + sc + 0] = tf32r(va.x);
            As[rr * 36 + sc + 1] = tf32r(va.y);
            As[rr * 36 + sc + 2] = tf32r(va.z);
            As[rr * 36 + sc + 3] = tf32r(va.w);
            Bs[rr * 36 + sc + 0] = tf32r(vb.x);
            Bs[rr * 36 + sc + 1] = tf32r(vb.y);
            Bs[rr * 36 + sc + 2] = tf32r(vb.z);
            Bs[rr * 36 + sc + 3] = tf32r(vb.w);
        }
        __syncthreads();

#pragma unroll
        for (int kk = 0; kk < 32; kk += 8) {
            uint32_t a[2][4];
#pragma unroll
            for (int mt = 0; mt < 2; mt++) {
                int ar = wm * 32 + mt * 16 + (lane >> 2);
                int ac = kk + (lane & 3);
                a[mt][0] = __float_as_uint(As[ar * 36 + ac]);
                a[mt][1] = __float_as_uint(As[(ar + 8) * 36 + ac]);
                a[mt][2] = __float_as_uint(As[ar * 36 + ac + 4]);
                a[mt][3] = __float_as_uint(As[(ar + 8) * 36 + ac + 4]);
            }
#pragma unroll
            for (int t = 0; t < 8; t++) {
                int br = wn * 64 + t * 8 + (lane >> 2);
                int bc = kk + (lane & 3);
                uint32_t b0 = __float_as_uint(Bs[br * 36 + bc]);
                uint32_t b1 = __float_as_uint(Bs[br * 36 + bc + 4]);
                mma_tf32(acc[t], a[0], b0, b1);
                mma_tf32(acc[8 + t], a[1], b0, b1);
            }
        }
        __syncthreads();
    }

#pragma unroll
    for (int mt = 0; mt < 2; mt++) {
#pragma unroll
        for (int t = 0; t < 8; t++) {
            int r0 = rowBase + wm * 32 + mt * 16 + (lane >> 2);
            int c0 = colBase + wn * 64 + t * 8 + 2 * (lane & 3);
            float bb0 = 0.f, bb1 = 0.f;
            if (BIAS) { bb0 = bias[c0]; bb1 = bias[c0 + 1]; }
            float* d = acc[mt * 8 + t];
            *(float2*)&C[r0 * N + c0] = make_float2(d[0] + bb0, d[1] + bb1);
            *(float2*)&C[(r0 + 8) * N + c0] = make_float2(d[2] + bb0, d[3] + bb1);
        }
    }
}

// ---------------------------------------------------------------------------
// RoPE, in place on Q and K.
// ---------------------------------------------------------------------------
__global__ void rope_kernel(float* __restrict__ Q, float* __restrict__ K,
                            const int* __restrict__ pos_ids) {
    int idx = blockIdx.x * blockDim.x + threadIdx.x;
    const int total = SEQ * NH * (HD / 2);
    if (idx >= total) return;
    int j = idx & 31;
    int h = (idx >> 5) & (NH - 1);
    int s = idx >> 9;

    float pos = (float)pos_ids[s];
    float theta = expf(-(float)j * (9.210340371976184f / 32.0f));
    float ang = pos * theta;
    float sn, cs;
    sincosf(ang, &sn, &cs);

    int base = s * HID + h * HD + j;
    float q1 = Q[base], q2 = Q[base + 32];
    Q[base]      = q1 * cs - q2 * sn;
    Q[base + 32] = q1 * sn + q2 * cs;
    float k1 = K[base], k2 = K[base + 32];
    K[base]      = k1 * cs - k2 * sn;
    K[base + 32] = k1 * sn + k2 * cs;
}

// ---------------------------------------------------------------------------
// Causal flash attention, tf32 MMA. BR=128, BC=64, hd=64.
// 8 warps; warp w owns rows [16w, 16w+16).
// Qs/Ks/Ps pitch 68 (conflict-free for row-by-(lane>>2) access);
// Vs pitch 72 (conflict-free for k-by-(lane&3) access in PV).
// ---------------------------------------------------------------------------
__global__ __launch_bounds__(256)
void flash_attn(const float* __restrict__ Q, const float* __restrict__ K,
                const float* __restrict__ V, float* __restrict__ O) {
    extern __shared__ float sm[];
    float* Qs = sm;                   // 128 x 68
    float* Ks = Qs + 128 * 68;        // 64 x 68
    float* Vs = Ks + 64 * 68;         // 64 x 72
    float* Ps = Vs + 64 * 72;         // 128 x 68
    float* mrow = Ps + 128 * 68;      // 128
    float* lrow = mrow + 128;         // 128
    float* arow = lrow + 128;         // 128

    const int tid = threadIdx.x;
    const int lane = tid & 31;
    const int w = tid >> 5;
    const int qb = gridDim.x - 1 - blockIdx.x;   // heavy blocks first
    const int h = blockIdx.y;
    const int qBase = qb * 128;
    const float scale = 0.125f;

    // stage Q (tf32-rounded)
    for (int i = tid; i < 128 * 16; i += 256) {
        int r = i >> 4, q4 = (i & 15) * 4;
        float4 v = *(const float4*)&Q[(qBase + r) * HID + h * HD + q4];
        Qs[r * 68 + q4 + 0] = tf32r(v.x);
        Qs[r * 68 + q4 + 1] = tf32r(v.y);
        Qs[r * 68 + q4 + 2] = tf32r(v.z);
        Qs[r * 68 + q4 + 3] = tf32r(v.w);
    }
    if (tid < 128) { mrow[tid] = -1e30f; lrow[tid] = 0.f; }

    float o[8][4];
#pragma unroll
    for (int t = 0; t < 8; t++)
#pragma unroll
        for (int j = 0; j < 4; j++) o[t][j] = 0.f;

    const int nkb = 2 * qb + 2;
    for (int kb = 0; kb < nkb; kb++) {
        const int kBase = kb * 64;
        for (int i = tid; i < 64 * 16; i += 256) {
            int r = i >> 4, q4 = (i & 15) * 4;
            float4 vk = *(const float4*)&K[(kBase + r) * HID + h * HD + q4];
            float4 vv = *(const float4*)&V[(kBase + r) * HID + h * HD + q4];
            Ks[r * 68 + q4 + 0] = tf32r(vk.x);
            Ks[r * 68 + q4 + 1] = tf32r(vk.y);
            Ks[r * 68 + q4 + 2] = tf32r(vk.z);
            Ks[r * 68 + q4 + 3] = tf32r(vk.w);
            Vs[r * 72 + q4 + 0] = tf32r(vv.x);
            Vs[r * 72 + q4 + 1] = tf32r(vv.y);
            Vs[r * 72 + q4 + 2] = tf32r(vv.z);
            Vs[r * 72 + q4 + 3] = tf32r(vv.w);
        }
        __syncthreads();   // Q/K/V staged, m/l init visible

        // ---- S = Q K^T, warp rows 16w..16w+15, all 64 cols ----
        float sfrag[8][4];
#pragma unroll
        for (int t = 0; t < 8; t++)
#pragma unroll
            for (int j = 0; j < 4; j++) sfrag[t][j] = 0.f;

#pragma unroll
        for (int kk = 0; kk < 64; kk += 8) {
            uint32_t a[4];
            int ar = (w << 4) + (lane >> 2);
            int ac = kk + (lane & 3);
            a[0] = __float_as_uint(Qs[ar * 68 + ac]);
            a[1] = __float_as_uint(Qs[(ar + 8) * 68 + ac]);
            a[2] = __float_as_uint(Qs[ar * 68 + ac + 4]);
            a[3] = __float_as_uint(Qs[(ar + 8) * 68 + ac + 4]);
#pragma unroll
            for (int t = 0; t < 8; t++) {
                int br = t * 8 + (lane >> 2);
                uint32_t b0 = __float_as_uint(Ks[br * 68 + ac]);
                uint32_t b1 = __float_as_uint(Ks[br * 68 + ac + 4]);
                mma_tf32(sfrag[t], a, b0, b1);
            }
        }

        // ---- scale + causal mask -> Ps ----
        {
            int r0 = (w << 4) + (lane >> 2);
            int r1 = r0 + 8;
            int qg0 = qBase + r0, qg1 = qBase + r1;
#pragma unroll
            for (int t = 0; t < 8; t++) {
                int c = t * 8 + 2 * (lane & 3);
                int kg = kBase + c;
                float v0 = sfrag[t][0] * scale; if (kg     > qg0) v0 = -1e30f;
                float v1 = sfrag[t][1] * scale; if (kg + 1 > qg0) v1 = -1e30f;
                float v2 = sfrag[t][2] * scale; if (kg     > qg1) v2 = -1e30f;
                float v3 = sfrag[t][3] * scale; if (kg + 1 > qg1) v3 = -1e30f;
                *(float2*)&Ps[r0 * 68 + c] = make_float2(v0, v1);
                *(float2*)&Ps[r1 * 68 + c] = make_float2(v2, v3);
            }
        }
        __syncwarp();

        // ---- online softmax: 2 lanes per row within the owning warp ----
        {
            int srow = (w << 4) + (lane >> 1);
            int half = lane & 1;
            float* prow = &Ps[srow * 68 + half * 32];
            float mx = -1e30f;
#pragma unroll 8
            for (int c = 0; c < 32; c++) mx = fmaxf(mx, prow[c]);
            mx = fmaxf(mx, __shfl_xor_sync(0xffffffffu, mx, 1));
            float mold = mrow[srow];
            float mnew = fmaxf(mold, mx);
            float sum = 0.f;
#pragma unroll 8
            for (int c = 0; c < 32; c++) {
                float p = tf32r(__expf(prow[c] - mnew));
                prow[c] = p;
                sum += p;
            }
            sum += __shfl_xor_sync(0xffffffffu, sum, 1);
            if (!half) {
                float alpha = __expf(mold - mnew);
                arow[srow] = alpha;
                mrow[srow] = mnew;
                lrow[srow] = lrow[srow] * alpha + sum;
            }
        }
        __syncwarp();

        // ---- O = alpha*O + P V ----
        {
            float a0 = arow[(w << 4) + (lane >> 2)];
            float a1 = arow[(w << 4) + (lane >> 2) + 8];
#pragma unroll
            for (int t = 0; t < 8; t++) {
                o[t][0] *= a0; o[t][1] *= a0;
                o[t][2] *= a1; o[t][3] *= a1;
            }
#pragma unroll
            for (int kk = 0; kk < 64; kk += 8) {
                uint32_t a[4];
                int ar = (w << 4) + (lane >> 2);
                int ac = kk + (lane & 3);
                a[0] = __float_as_uint(Ps[ar * 68 + ac]);
                a[1] = __float_as_uint(Ps[(ar + 8) * 68 + ac]);
                a[2] = __float_as_uint(Ps[ar * 68 + ac + 4]);
                a[3] = __float_as_uint(Ps[(ar + 8) * 68 + ac + 4]);
#pragma unroll
                for (int t = 0; t < 8; t++) {
                    int bn = t * 8 + (lane >> 2);
                    uint32_t b0 = __float_as_uint(Vs[(ac) * 72 + bn]);
                    uint32_t b1 = __float_as_uint(Vs[(ac + 4) * 72 + bn]);
                    mma_tf32(o[t], a, b0, b1);
                }
            }
        }
        __syncthreads();   // protect Ks/Vs restaging next iteration
    }

    // ---- normalize + write out ----
    {
        int r0 = (w << 4) + (lane >> 2);
        float inv0 = 1.f / lrow[r0];
        float inv1 = 1.f / lrow[r0 + 8];
        int gr0 = qBase + r0;
#pragma unroll
        for (int t = 0; t < 8; t++) {
            int c = h * HD + t * 8 + 2 * (lane & 3);
            *(float2*)&O[gr0 * HID + c] = make_float2(o[t][0] * inv0, o[t][1] * inv0);
            *(float2*)&O[(gr0 + 8) * HID + c] = make_float2(o[t][2] * inv1, o[t][3] * inv1);
        }
    }
}

// ---------------------------------------------------------------------------
// Host launcher. Inputs: 0:X 1:position_ids 2:mask(unused) 3:Wq 4:Wk 5:Wv
//                        6:Wo 7:bo ; output f32[1,4096,1024]
// ---------------------------------------------------------------------------
extern "C" void kernel_launch(void* const* d_in, const int* in_sizes, int n_in,
                              void* d_out, int out_size) {
    const float* X  = (const float*)d_in[0];
    const int* pos  = (const int*)d_in[1];
    const float* Wq = (const float*)d_in[3];
    const float* Wk = (const float*)d_in[4];
    const float* Wv = (const float*)d_in[5];
    const float* Wo = (const float*)d_in[6];
    const float* bo = (const float*)d_in[7];
    float* out = (float*)d_out;

    float *Qd, *Kd, *Vd, *Cd;
    cudaGetSymbolAddress((void**)&Qd, g_Q);
    cudaGetSymbolAddress((void**)&Kd, g_K);
    cudaGetSymbolAddress((void**)&Vd, g_V);
    cudaGetSymbolAddress((void**)&Cd, g_C);

    dim3 ggrid(HID / 128, SEQ / 128);  // (8, 32)

    gemm_tf32<false><<<ggrid, 256>>>(X, Wq, nullptr, Qd, SEQ, HID, HID);
    gemm_tf32<false><<<ggrid, 256>>>(X, Wk, nullptr, Kd, SEQ, HID, HID);
    gemm_tf32<false><<<ggrid, 256>>>(X, Wv, nullptr, Vd, SEQ, HID, HID);

    rope_kernel<<<(SEQ * NH * (HD / 2) + 255) / 256, 256>>>(Qd, Kd, pos);

    const int flash_smem = (128 * 68 + 64 * 68 + 64 * 72 + 128 * 68 + 3 * 128) * (int)sizeof(float);
    cudaFuncSetAttribute(flash_attn, cudaFuncAttributeMaxDynamicSharedMemorySize, flash_smem);
    flash_attn<<<dim3(SEQ / 128, NH), 256, flash_smem>>>(Qd, Kd, Vd, Cd);

    gemm_tf32<true><<<ggrid, 256>>>(Cd, Wo, bo, out, SEQ, HID, HID);
}